// round 15
// baseline (speedup 1.0000x reference)
#include <cuda_runtime.h>
#include <cuda_fp16.h>
#include <cstdint>

#define T_STEPS 256
#define BATCH   16
#define HID     100
#define G4      400
#define VOCAB   30522
#define M_ROWS  4096   // T*B
#define KP      112    // K padded to 7 x 16

// Vocab GEMM tiling (fused kernel)
#define MT    128
#define NT    192
#define NBLK  159               // ceil(VOCAB/192)
#define NPAD  (NBLK * NT)       // 30528
#define N16B  (NPAD / 16)       // 1908 n16-blocks
#define SEG_M 4                 // m-tiles per segment -> 512-row chunks
#define NCHK  8
#define NSEG  (NCHK * NBLK)     // 1272
#define ROWB  240               // smem row bytes for gx kernel
#define ROWW  60

// gx GEMM tiling
#define GXM   128
#define GXN   224

// ---------------------------------------------------------------------------
// Device scratch
// ---------------------------------------------------------------------------
__device__ float g_gx[(size_t)M_ROWS * G4];
// A in mma-fragment order: [m16-block q (=t)][ks][lane] -> 16B {a0,a1,a2,a3}
__device__ uint4 gAf[(size_t)T_STEPS * 7 * 32];
// W in mma-fragment order: [n16-block][ks][lane] -> 16B {b0,b1 (n), b0,b1 (n+8)}
__device__ uint4 gWf[(size_t)N16B * 7 * 32];
__device__ __align__(16) __half gE_hi[(size_t)M_ROWS * KP];
__device__ __align__(16) __half gE_lo[(size_t)M_ROWS * KP];
__device__ __align__(16) __half gWih_hi[(size_t)448 * KP];
__device__ __align__(16) __half gWih_lo[(size_t)448 * KP];
__device__ int g_counter;
__device__ int g_prog[BATCH * 32];   // padded: one 128B line per batch element

// ---------------------------------------------------------------------------
// helpers
// ---------------------------------------------------------------------------
__device__ __forceinline__ uint32_t smem_u32(const void* p) {
    uint32_t a;
    asm("{ .reg .u64 t; cvta.to.shared.u64 t, %1; cvt.u32.u64 %0, t; }"
        : "=r"(a) : "l"(p));
    return a;
}
__device__ __forceinline__ void cp16(uint32_t dst, const void* src) {
    asm volatile("cp.async.ca.shared.global [%0], [%1], 16;" :: "r"(dst), "l"(src));
}
__device__ __forceinline__ void mma_fp16(float* c, const uint32_t* a,
                                         uint32_t b0, uint32_t b1) {
    asm volatile(
        "mma.sync.aligned.m16n8k16.row.col.f32.f16.f16.f32 "
        "{%0,%1,%2,%3},{%4,%5,%6,%7},{%8,%9},{%0,%1,%2,%3};\n"
        : "+f"(c[0]), "+f"(c[1]), "+f"(c[2]), "+f"(c[3])
        : "r"(a[0]), "r"(a[1]), "r"(a[2]), "r"(a[3]), "r"(b0), "r"(b1));
}
__device__ __forceinline__ void stg_cs2(float* p, float x, float y) {
    asm volatile("st.global.cs.v2.f32 [%0], {%1, %2};"
                 :: "l"(p), "f"(x), "f"(y) : "memory");
}
__device__ __forceinline__ void fma2(unsigned long long& acc,
                                     unsigned long long a,
                                     unsigned long long b) {
    asm("fma.rn.f32x2 %0, %1, %2, %0;" : "+l"(acc) : "l"(a), "l"(b));
}
__device__ __forceinline__ float unpack_sum(unsigned long long a) {
    float lo, hi;
    asm("mov.b64 {%0, %1}, %2;" : "=f"(lo), "=f"(hi) : "l"(a));
    return lo + hi;
}

__device__ __forceinline__ void split8(const float* v, uint32_t* ph, uint32_t* pl) {
    #pragma unroll
    for (int j = 0; j < 4; j++) {
        __half h0 = __float2half_rn(v[2*j]);
        __half h1 = __float2half_rn(v[2*j+1]);
        __half l0 = __float2half_rn(v[2*j]   - __half2float(h0));
        __half l1 = __float2half_rn(v[2*j+1] - __half2float(h1));
        ph[j] = (uint32_t)__half_as_ushort(h0) | ((uint32_t)__half_as_ushort(h1) << 16);
        pl[j] = (uint32_t)__half_as_ushort(l0) | ((uint32_t)__half_as_ushort(l1) << 16);
    }
}
__device__ __forceinline__ int ld_acq(const int* p) {
    int v;
    asm volatile("ld.acquire.gpu.global.b32 %0, [%1];" : "=r"(v) : "l"(p) : "memory");
    return v;
}
__device__ __forceinline__ void st_rel(int* p, int v) {
    asm volatile("st.release.gpu.global.b32 [%0], %1;" :: "l"(p), "r"(v) : "memory");
}

// ---------------------------------------------------------------------------
// Kernel 0: presplit. emb gather -> gE hi/lo; W_ih -> gWih hi/lo;
// out_W -> gWf (fragment order, fp16 hi). + reset counter/progress.
// ---------------------------------------------------------------------------
#define U_E    (M_ROWS * 14)
#define U_WIH  (448 * 14)
#define U_W    (NPAD * 14)
#define U_TOT  (U_E + U_WIH + U_W)           // 491008 = 1918*256

__global__ __launch_bounds__(256) void presplit_kernel(
        const int* __restrict__ input, const float* __restrict__ emb,
        const float* __restrict__ dec_W_ih, const float* __restrict__ out_W) {
    if (blockIdx.x == 0) {
        if (threadIdx.x < BATCH) g_prog[threadIdx.x * 32] = 0;
        if (threadIdx.x == BATCH) g_counter = 0;
    }
    const int u = blockIdx.x * 256 + threadIdx.x;
    float v[8];
    uint32_t ph[4], pl[4];

    if (u < U_E) {
        int row = u / 14, k0 = (u % 14) * 8;
        const float* src = emb + (size_t)input[row] * HID;
        #pragma unroll
        for (int i = 0; i < 8; i++) {
            int k = k0 + i;
            v[i] = (k < HID) ? src[k] : 0.f;
        }
        split8(v, ph, pl);
        size_t d = (size_t)row * KP + k0;
        *(uint4*)(gE_hi + d) = make_uint4(ph[0], ph[1], ph[2], ph[3]);
        *(uint4*)(gE_lo + d) = make_uint4(pl[0], pl[1], pl[2], pl[3]);
    } else if (u < U_E + U_WIH) {
        int w = u - U_E;
        int row = w / 14, k0 = (w % 14) * 8;
        #pragma unroll
        for (int i = 0; i < 8; i++) {
            int k = k0 + i;
            v[i] = (row < G4 && k < HID) ? dec_W_ih[(size_t)row * HID + k] : 0.f;
        }
        split8(v, ph, pl);
        size_t d = (size_t)row * KP + k0;
        *(uint4*)(gWih_hi + d) = make_uint4(ph[0], ph[1], ph[2], ph[3]);
        *(uint4*)(gWih_lo + d) = make_uint4(pl[0], pl[1], pl[2], pl[3]);
    } else {
        // out_W row 'row', k-unit of 8 -> fragment-order half2 stores
        int w = u - U_E - U_WIH;
        int row = w / 14, k0 = (w % 14) * 8;
        int ks = k0 >> 4, hi8 = (k0 >> 3) & 1;
        int nb16 = row >> 4, sub = (row >> 3) & 1;
        int lanebase = (row & 7) << 2;
        char* base = (char*)gWf + ((((size_t)nb16 * 7 + ks) << 9));
        #pragma unroll
        for (int tig = 0; tig < 4; tig++) {
            int k = k0 + tig * 2;
            float v0 = (row < VOCAB && k < HID)
                           ? out_W[(size_t)row * HID + k] : 0.f;
            float v1 = (row < VOCAB && k + 1 < HID)
                           ? out_W[(size_t)row * HID + k + 1] : 0.f;
            __half2 hh = __floats2half2_rn(v0, v1);
            *(__half2*)(base + ((lanebase + tig) << 4) + ((sub * 2 + hi8) << 2)) = hh;
        }
    }
}

// ---------------------------------------------------------------------------
// Kernel 1: gx via HMMA (3-term split, precision load-bearing). Grid 64.
// ---------------------------------------------------------------------------
#define SMX_BIAS 0
#define SMX_A    1024
#define SMX_B    (SMX_A + 2 * GXM * ROWB)
#define SMX_TOT  (SMX_B + 2 * GXN * ROWB)    // 169984

__global__ __launch_bounds__(256, 1) void gx_mma_kernel(
        const float* __restrict__ b_ih, const float* __restrict__ b_hh) {
    extern __shared__ char sm[];
    const uint32_t sb = smem_u32(sm);
    const int tid = threadIdx.x;
    const int nblk = blockIdx.x & 1, mt = blockIdx.x >> 1;
    const int m0 = mt * GXM, n0 = nblk * GXN;

    for (int c = tid; c < GXN; c += 256) {
        int j = n0 + c;
        ((float*)(sm + SMX_BIAS))[c] = (j < G4) ? b_ih[j] + b_hh[j] : 0.f;
    }
    for (int e = tid; e < 3584; e += 256) {
        int arr = e >= 1792, r = (e - arr * 1792) / 14, c = e % 14;
        const __half* src = (arr ? gE_lo : gE_hi) + (size_t)(m0 + r) * KP + c * 8;
        cp16(sb + SMX_A + arr * 30720 + r * ROWB + c * 16, src);
    }
    for (int e = tid; e < 6272; e += 256) {
        int arr = e >= 3136, r = (e - arr * 3136) / 14, c = e % 14;
        const __half* src = (arr ? gWih_lo : gWih_hi) + (size_t)(n0 + r) * KP + c * 8;
        cp16(sb + SMX_B + arr * 53760 + r * ROWB + c * 16, src);
    }
    asm volatile("cp.async.commit_group;");
    asm volatile("cp.async.wait_group 0;");
    __syncthreads();

    const int wid = tid >> 5, lane = tid & 31;
    const int wm = wid >> 2, wn = wid & 3;
    const int gid = lane >> 2, tig = lane & 3;
    const uint32_t* A32 = (const uint32_t*)(sm + SMX_A);
    const uint32_t* B32 = (const uint32_t*)(sm + SMX_B);

    float acc[4][7][4];
    #pragma unroll
    for (int mb = 0; mb < 4; mb++)
        #pragma unroll
        for (int nb = 0; nb < 7; nb++)
            #pragma unroll
            for (int q = 0; q < 4; q++) acc[mb][nb][q] = 0.f;

    #pragma unroll 1
    for (int ks = 0; ks < 7; ks++) {
        uint32_t ah[4][4], al[4][4];
        #pragma unroll
        for (int mb = 0; mb < 4; mb++) {
            int w = (wm * 64 + mb * 16 + gid) * ROWW + ks * 8 + tig;
            ah[mb][0] = A32[w];            al[mb][0] = A32[w + 7680];
            ah[mb][1] = A32[w + 8 * ROWW]; al[mb][1] = A32[w + 7680 + 8 * ROWW];
            ah[mb][2] = A32[w + 4];        al[mb][2] = A32[w + 7680 + 4];
            ah[mb][3] = A32[w + 8 * ROWW + 4];
            al[mb][3] = A32[w + 7680 + 8 * ROWW + 4];
        }
        #pragma unroll
        for (int nb = 0; nb < 7; nb++) {
            int w = (wn * 56 + nb * 8 + gid) * ROWW + ks * 8 + tig;
            uint32_t bh0 = B32[w], bh1 = B32[w + 4];
            uint32_t bl0 = B32[w + 13440], bl1 = B32[w + 13440 + 4];
            #pragma unroll
            for (int mb = 0; mb < 4; mb++) {
                mma_fp16(acc[mb][nb], ah[mb], bh0, bh1);
                mma_fp16(acc[mb][nb], ah[mb], bl0, bl1);
                mma_fp16(acc[mb][nb], al[mb], bh0, bh1);
            }
        }
    }

    const float* biasS = (const float*)(sm + SMX_BIAS);
    #pragma unroll
    for (int nb = 0; nb < 7; nb++) {
        int jl = wn * 56 + nb * 8 + tig * 2;
        int j  = n0 + jl;
        if (j < G4) {
            float b0 = biasS[jl], b1 = biasS[jl + 1];
            #pragma unroll
            for (int mb = 0; mb < 4; mb++) {
                int row = m0 + wm * 64 + mb * 16 + gid;
                *(float2*)(g_gx + (size_t)row * G4 + j) =
                    make_float2(acc[mb][nb][0] + b0, acc[mb][nb][1] + b1);
                *(float2*)(g_gx + (size_t)(row + 8) * G4 + j) =
                    make_float2(acc[mb][nb][2] + b0, acc[mb][nb][3] + b1);
            }
        }
    }
}

// ---------------------------------------------------------------------------
// Kernel 2 (FUSED): blocks 0..15 = LSTM producer (warp-local gate mapping,
// shfl exchange, double-buffered h, gx prefetched, 4 fma2 chains);
// blocks 16..147 = persistent fragment-LDG GEMM with a register-double-
// buffered (software-pipelined) k-loop and streaming stores.
// ---------------------------------------------------------------------------
#define FS_BIAS 0                      // 192 floats
#define FS_SEG  1000                   // scratch int (GEMM phase only)
// LSTM smem: h ping@0 (448B), pong@448; h_hist@1024 (3584B); gxbuf@4608
#define LS_HIST 1024
#define LS_GXB  4608
#define LS_GXSZ 25600                  // 16 steps x 400 floats
#define FS_TOT  (LS_GXB + 2 * LS_GXSZ) // 55808

__device__ __forceinline__ void poll_need(int need) {
    if (threadIdx.x == 0) {
        for (;;) {
            int mn = 0x7fffffff;
            #pragma unroll
            for (int q = 0; q < BATCH; q++) mn = min(mn, ld_acq(&g_prog[q * 32]));
            if (mn >= need) break;
            __nanosleep(128);
        }
    }
    __syncthreads();
}

__global__ __launch_bounds__(416, 1) void fused_kernel(
        const float* __restrict__ W_hh,
        const float* __restrict__ out_b,
        float* __restrict__ out) {
    extern __shared__ char sm[];
    const uint32_t sb = smem_u32(sm);
    const int tid = threadIdx.x;

    if (blockIdx.x < BATCH) {
        // ===================== LSTM producer =====================
        float* h_hist = (float*)(sm + LS_HIST);    // 8 x 112 floats
        const float* gxb = (const float*)(sm + LS_GXB);
        const int b = blockIdx.x;

        const int w_ = tid >> 5, l = tid & 31;
        const int jloc = l & 7, gate = l >> 3;
        const int j = w_ * 8 + jloc;               // hidden unit
        const bool jvalid = (j < HID);
        const int grow = gate * HID + j;           // W_hh row / gx index

        // W row in registers: 100 floats = 25 x ulonglong2 (16B aligned)
        ulonglong2 w4[25];
        if (jvalid) {
            const ulonglong2* wg =
                (const ulonglong2*)(W_hh + (size_t)grow * HID);
            #pragma unroll
            for (int k = 0; k < 25; k++) w4[k] = wg[k];
        }
        if (tid < HID) ((float*)sm)[tid] = 0.f;    // h buf0 = 0
        if (tid < 96) {                            // zero h_hist k-padding
            int s = tid / 12, k = 100 + (tid % 12);
            h_hist[s * KP + k] = 0.f;
        }
        float c = 0.f;

        // prefetch gx chunk 0 (16 steps)
        {
            const uint32_t dst0 = sb + LS_GXB;
            for (int e = tid; e < 1600; e += 416) {
                int row = e / 100, u = e % 100;
                cp16(dst0 + row * 1600 + u * 16,
                     g_gx + ((size_t)row * BATCH + b) * G4 + u * 4);
            }
            asm volatile("cp.async.commit_group;");
            asm volatile("cp.async.wait_group 0;");
        }
        __syncthreads();

        for (int t = 0; t < T_STEPS; t++) {
            if ((t & 15) == 0 && t + 16 < T_STEPS) {
                const int t1 = t + 16;
                const uint32_t dst = sb + LS_GXB + (((t1 >> 4) & 1) ? LS_GXSZ : 0);
                for (int e = tid; e < 1600; e += 416) {
                    int row = e / 100, u = e % 100;
                    cp16(dst + row * 1600 + u * 16,
                         g_gx + ((size_t)(t1 + row) * BATCH + b) * G4 + u * 4);
                }
                asm volatile("cp.async.commit_group;");
            }

            float a = 0.f;
            {
                const ulonglong2* h2 =
                    (const ulonglong2*)(sm + (t & 1) * 448);
                unsigned long long acc0, acc1, acc2, acc3;
                asm("mov.b64 %0, {%1, %1};" : "=l"(acc0) : "r"(0));
                asm("mov.b64 %0, {%1, %1};" : "=l"(acc1) : "r"(0));
                asm("mov.b64 %0, {%1, %1};" : "=l"(acc2) : "r"(0));
                asm("mov.b64 %0, {%1, %1};" : "=l"(acc3) : "r"(0));
                if (jvalid) {
                    #pragma unroll
                    for (int k = 0; k < 25; k++) {
                        ulonglong2 hv = h2[k];
                        if (k & 1) { fma2(acc2, w4[k].x, hv.x);
                                     fma2(acc3, w4[k].y, hv.y); }
                        else       { fma2(acc0, w4[k].x, hv.x);
                                     fma2(acc1, w4[k].y, hv.y); }
                    }
                    float gcur = gxb[((t >> 4) & 1) * 6400 + (t & 15) * 400 + grow];
                    float d = gcur + (unpack_sum(acc0) + unpack_sum(acc1))
                                   + (unpack_sum(acc2) + unpack_sum(acc3));
                    // uniform activation: g-gate tanh(d); others 0.5+0.5*tanh(d/2)
                    float arg = (gate == 2) ? d : 0.5f * d;
                    float th  = tanhf(arg);
                    a = (gate == 2) ? th : (0.5f + 0.5f * th);
                }
            }
            // exchange gates within the warp (all lanes participate)
            float ig = __shfl_sync(0xffffffffu, a, jloc);
            float fg = __shfl_sync(0xffffffffu, a, jloc + 8);
            float gg = __shfl_sync(0xffffffffu, a, jloc + 16);
            float og = __shfl_sync(0xffffffffu, a, jloc + 24);

            if (gate == 0 && jvalid) {
                c = fg * c + ig * gg;
                float hn = og * tanhf(c);
                ((float*)(sm + ((t + 1) & 1) * 448))[j] = hn;
                h_hist[(t & 7) * KP + j] = hn;
            }
            __syncthreads();   // h writes + hist visible; safe to read next step

            if ((t & 7) == 7) {
                // flush 8 steps as fragment-order half2 stores
                if (tid < 224) {
                    const int lane_b = ((b & 7) << 2);
                    const int off_b  = ((b >> 3) << 2);
                    #pragma unroll
                    for (int rep = 0; rep < 2; rep++) {
                        int i  = tid + rep * 224;          // 0..447
                        int s  = i / 56;
                        int kp = i % 56;
                        int ks = kp >> 3, kk = kp & 7;
                        int tg = kk & 3, hi8 = kk >> 2;
                        int kb = ks * 16 + hi8 * 8 + tg * 2;
                        __half2 hh = __floats2half2_rn(
                            h_hist[s * KP + kb], h_hist[s * KP + kb + 1]);
                        char* dst = (char*)gAf +
                            (((size_t)(t - 7 + s) * 7 + ks) << 9) +
                            ((lane_b + tg) << 4) + off_b + (hi8 << 3);
                        *(__half2*)dst = hh;
                    }
                }
                __syncthreads();
                if (tid == 0) st_rel(&g_prog[b * 32], t + 1);
            }

            if ((t & 15) == 15 && t + 1 < T_STEPS) {
                asm volatile("cp.async.wait_group 0;");
                __syncthreads();
            }
        }
        __syncthreads();
        // fall through: help the GEMM with remaining segments
    }

    // ===================== GEMM consumer (pipelined fragment LDG) ==========
    const int wid = tid >> 5, lane = tid & 31;
    const int wm = (wid < 12) ? (wid / 6) : 0;     // 2(M) x 6(N), warps 0..11
    const int wn = (wid < 12) ? (wid % 6) : 0;
    const int gid = lane >> 2, tig = lane & 3;

    for (;;) {
        if (tid == 0) *(int*)(sm + FS_SEG) = atomicAdd(&g_counter, 1);
        __syncthreads();
        const int seg = *(const int*)(sm + FS_SEG);
        if (seg >= NSEG) break;
        const int mch  = seg / NBLK;          // chunk index (t-ordered)
        const int nblk = seg - mch * NBLK;
        const int n0   = nblk * NT;
        const int mt0  = mch * SEG_M;

        if (tid < NT) {
            int col = n0 + tid;
            ((float*)(sm + FS_BIAS))[tid] = (col < VOCAB) ? out_b[col] : 0.f;
        }

        #pragma unroll 1
        for (int it = 0; it < SEG_M; it++) {
            poll_need((mt0 + it + 1) * 8);   // includes __syncthreads

            if (wid < 12) {
                const int q0  = (mt0 + it) * 8 + wm * 4;   // m16-block base
                const int nb0 = (n0 >> 4) + wn * 2;        // n16-block base
                const uint4* aP = gAf + (size_t)q0 * 7 * 32 + lane;
                const uint4* b0P = gWf + (size_t)nb0 * 7 * 32 + lane;
                const uint4* b1P = gWf + (size_t)(nb0 + 1) * 7 * 32 + lane;

                float acc[4][4][4];
                #pragma unroll
                for (int mb = 0; mb < 4; mb++)
                    #pragma unroll
                    for (int nb = 0; nb < 4; nb++)
                        #pragma unroll
                        for (int q = 0; q < 4; q++) acc[mb][nb][q] = 0.f;

                // software pipeline: prefetch ks+1 fragments while MMA ks
                uint4 aC[4], B0C, B1C;
                #pragma unroll
                for (int mb = 0; mb < 4; mb++) aC[mb] = aP[mb * 7 * 32];
                B0C = b0P[0];
                B1C = b1P[0];

                #pragma unroll
                for (int ks = 0; ks < 7; ks++) {
                    uint4 aN[4], B0N, B1N;
                    if (ks < 6) {
                        #pragma unroll
                        for (int mb = 0; mb < 4; mb++)
                            aN[mb] = aP[mb * 7 * 32 + (ks + 1) * 32];
                        B0N = b0P[(ks + 1) * 32];
                        B1N = b1P[(ks + 1) * 32];
                    }
                    #pragma unroll
                    for (int mb = 0; mb < 4; mb++) {
                        const uint32_t* am = (const uint32_t*)&aC[mb];
                        mma_fp16(acc[mb][0], am, B0C.x, B0C.y);
                        mma_fp16(acc[mb][1], am, B0C.z, B0C.w);
                        mma_fp16(acc[mb][2], am, B1C.x, B1C.y);
                        mma_fp16(acc[mb][3], am, B1C.z, B1C.w);
                    }
                    if (ks < 6) {
                        #pragma unroll
                        for (int mb = 0; mb < 4; mb++) aC[mb] = aN[mb];
                        B0C = B0N;
                        B1C = B1N;
                    }
                }

                const int m0 = (mt0 + it) * MT;
                const float* biasS = (const float*)(sm + FS_BIAS);
                #pragma unroll
                for (int nb = 0; nb < 4; nb++) {
                    int cl  = wn * 32 + nb * 8 + tig * 2;
                    int col = n0 + cl;
                    if (col < VOCAB) {
                        float b0 = biasS[cl], b1 = biasS[cl + 1];
                        #pragma unroll
                        for (int mb = 0; mb < 4; mb++) {
                            int row = m0 + wm * 64 + mb * 16 + gid;
                            stg_cs2(out + (size_t)row * VOCAB + col,
                                    acc[mb][nb][0] + b0, acc[mb][nb][1] + b1);
                            stg_cs2(out + (size_t)(row + 8) * VOCAB + col,
                                    acc[mb][nb][2] + b0, acc[mb][nb][3] + b1);
                        }
                    }
                }
            }
        }
        __syncthreads();   // all reads of bias done before next segment rewrite
    }
}

// ---------------------------------------------------------------------------
// Launch. Inputs: 0 input, 1 emb, 2..5 enc_* (dead), 6 dec_W_ih, 7 dec_W_hh,
// 8 dec_b_ih, 9 dec_b_hh, 10 out_W, 11 out_b.
// ---------------------------------------------------------------------------
extern "C" void kernel_launch(void* const* d_in, const int* in_sizes, int n_in,
                              void* d_out, int out_size) {
    (void)in_sizes; (void)n_in; (void)out_size;
    const int*   input = (const int*)d_in[0];
    const float* emb   = (const float*)d_in[1];
    const float* dWih  = (const float*)d_in[6];
    const float* dWhh  = (const float*)d_in[7];
    const float* dbih  = (const float*)d_in[8];
    const float* dbhh  = (const float*)d_in[9];
    const float* outW  = (const float*)d_in[10];
    const float* outb  = (const float*)d_in[11];
    float* out = (float*)d_out;

    cudaFuncSetAttribute(gx_mma_kernel,
                         cudaFuncAttributeMaxDynamicSharedMemorySize, SMX_TOT);
    cudaFuncSetAttribute(fused_kernel,
                         cudaFuncAttributeMaxDynamicSharedMemorySize, FS_TOT);

    presplit_kernel<<<U_TOT / 256, 256>>>(input, emb, dWih, outW);
    gx_mma_kernel<<<64, 256, SMX_TOT>>>(dbih, dbhh);
    fused_kernel<<<148, 416, FS_TOT>>>(dWhh, outb, out);
}

// round 16
// speedup vs baseline: 1.2168x; 1.2168x over previous
#include <cuda_runtime.h>
#include <cuda_fp16.h>
#include <cstdint>

#define T_STEPS 256
#define BATCH   16
#define HID     100
#define G4      400
#define VOCAB   30522
#define M_ROWS  4096   // T*B
#define KP      112    // K padded to 7 x 16

// Vocab GEMM tiling (fused kernel)
#define MT    128
#define NT    192
#define NBLK  159               // ceil(VOCAB/192)
#define NPAD  (NBLK * NT)       // 30528
#define N16B  (NPAD / 16)       // 1908 n16-blocks
#define SEG_M 4                 // m-tiles per segment -> 512-row chunks
#define NCHK  8
#define NSEG  (NCHK * NBLK)     // 1272
#define ROWB  240               // smem row bytes for gx kernel
#define ROWW  60

// gx GEMM tiling
#define GXM   128
#define GXN   224

// ---------------------------------------------------------------------------
// Device scratch
// ---------------------------------------------------------------------------
__device__ float g_gx[(size_t)M_ROWS * G4];
// A in mma-fragment order: [m16-block q (=t)][ks][lane] -> 16B {a0,a1,a2,a3}
__device__ uint4 gAf[(size_t)T_STEPS * 7 * 32];
// W in mma-fragment order: [n16-block][ks][lane] -> 16B {b0,b1 (n), b0,b1 (n+8)}
__device__ uint4 gWf[(size_t)N16B * 7 * 32];
__device__ __align__(16) __half gE_hi[(size_t)M_ROWS * KP];
__device__ __align__(16) __half gE_lo[(size_t)M_ROWS * KP];
__device__ __align__(16) __half gWih_hi[(size_t)448 * KP];
__device__ __align__(16) __half gWih_lo[(size_t)448 * KP];
__device__ int g_counter;
__device__ int g_done;           // SINGLE progress flag: +1 per LSTM CTA per 8 steps

// ---------------------------------------------------------------------------
// helpers
// ---------------------------------------------------------------------------
__device__ __forceinline__ uint32_t smem_u32(const void* p) {
    uint32_t a;
    asm("{ .reg .u64 t; cvta.to.shared.u64 t, %1; cvt.u32.u64 %0, t; }"
        : "=r"(a) : "l"(p));
    return a;
}
__device__ __forceinline__ void cp16(uint32_t dst, const void* src) {
    asm volatile("cp.async.ca.shared.global [%0], [%1], 16;" :: "r"(dst), "l"(src));
}
__device__ __forceinline__ void mma_fp16(float* c, const uint32_t* a,
                                         uint32_t b0, uint32_t b1) {
    asm volatile(
        "mma.sync.aligned.m16n8k16.row.col.f32.f16.f16.f32 "
        "{%0,%1,%2,%3},{%4,%5,%6,%7},{%8,%9},{%0,%1,%2,%3};\n"
        : "+f"(c[0]), "+f"(c[1]), "+f"(c[2]), "+f"(c[3])
        : "r"(a[0]), "r"(a[1]), "r"(a[2]), "r"(a[3]), "r"(b0), "r"(b1));
}
__device__ __forceinline__ void stg_cs2(float* p, float x, float y) {
    asm volatile("st.global.cs.v2.f32 [%0], {%1, %2};"
                 :: "l"(p), "f"(x), "f"(y) : "memory");
}
__device__ __forceinline__ void fma2(unsigned long long& acc,
                                     unsigned long long a,
                                     unsigned long long b) {
    asm("fma.rn.f32x2 %0, %1, %2, %0;" : "+l"(acc) : "l"(a), "l"(b));
}
__device__ __forceinline__ float unpack_sum(unsigned long long a) {
    float lo, hi;
    asm("mov.b64 {%0, %1}, %2;" : "=f"(lo), "=f"(hi) : "l"(a));
    return lo + hi;
}

__device__ __forceinline__ void split8(const float* v, uint32_t* ph, uint32_t* pl) {
    #pragma unroll
    for (int j = 0; j < 4; j++) {
        __half h0 = __float2half_rn(v[2*j]);
        __half h1 = __float2half_rn(v[2*j+1]);
        __half l0 = __float2half_rn(v[2*j]   - __half2float(h0));
        __half l1 = __float2half_rn(v[2*j+1] - __half2float(h1));
        ph[j] = (uint32_t)__half_as_ushort(h0) | ((uint32_t)__half_as_ushort(h1) << 16);
        pl[j] = (uint32_t)__half_as_ushort(l0) | ((uint32_t)__half_as_ushort(l1) << 16);
    }
}
__device__ __forceinline__ int ld_acq(const int* p) {
    int v;
    asm volatile("ld.acquire.gpu.global.b32 %0, [%1];" : "=r"(v) : "l"(p) : "memory");
    return v;
}
__device__ __forceinline__ void red_add_release(int* p, int v) {
    asm volatile("red.add.release.gpu.global.s32 [%0], %1;"
                 :: "l"(p), "r"(v) : "memory");
}

// ---------------------------------------------------------------------------
// Kernel 0: presplit. emb gather -> gE hi/lo; W_ih -> gWih hi/lo;
// out_W -> gWf (fragment order, fp16 hi). + reset counter/progress.
// ---------------------------------------------------------------------------
#define U_E    (M_ROWS * 14)
#define U_WIH  (448 * 14)
#define U_W    (NPAD * 14)
#define U_TOT  (U_E + U_WIH + U_W)           // 491008 = 1918*256

__global__ __launch_bounds__(256) void presplit_kernel(
        const int* __restrict__ input, const float* __restrict__ emb,
        const float* __restrict__ dec_W_ih, const float* __restrict__ out_W) {
    if (blockIdx.x == 0) {
        if (threadIdx.x == 0) g_done = 0;
        if (threadIdx.x == 1) g_counter = 0;
    }
    const int u = blockIdx.x * 256 + threadIdx.x;
    float v[8];
    uint32_t ph[4], pl[4];

    if (u < U_E) {
        int row = u / 14, k0 = (u % 14) * 8;
        const float* src = emb + (size_t)input[row] * HID;
        #pragma unroll
        for (int i = 0; i < 8; i++) {
            int k = k0 + i;
            v[i] = (k < HID) ? src[k] : 0.f;
        }
        split8(v, ph, pl);
        size_t d = (size_t)row * KP + k0;
        *(uint4*)(gE_hi + d) = make_uint4(ph[0], ph[1], ph[2], ph[3]);
        *(uint4*)(gE_lo + d) = make_uint4(pl[0], pl[1], pl[2], pl[3]);
    } else if (u < U_E + U_WIH) {
        int w = u - U_E;
        int row = w / 14, k0 = (w % 14) * 8;
        #pragma unroll
        for (int i = 0; i < 8; i++) {
            int k = k0 + i;
            v[i] = (row < G4 && k < HID) ? dec_W_ih[(size_t)row * HID + k] : 0.f;
        }
        split8(v, ph, pl);
        size_t d = (size_t)row * KP + k0;
        *(uint4*)(gWih_hi + d) = make_uint4(ph[0], ph[1], ph[2], ph[3]);
        *(uint4*)(gWih_lo + d) = make_uint4(pl[0], pl[1], pl[2], pl[3]);
    } else {
        // out_W row 'row', k-unit of 8 -> fragment-order half2 stores
        int w = u - U_E - U_WIH;
        int row = w / 14, k0 = (w % 14) * 8;
        int ks = k0 >> 4, hi8 = (k0 >> 3) & 1;
        int nb16 = row >> 4, sub = (row >> 3) & 1;
        int lanebase = (row & 7) << 2;
        char* base = (char*)gWf + ((((size_t)nb16 * 7 + ks) << 9));
        #pragma unroll
        for (int tig = 0; tig < 4; tig++) {
            int k = k0 + tig * 2;
            float v0 = (row < VOCAB && k < HID)
                           ? out_W[(size_t)row * HID + k] : 0.f;
            float v1 = (row < VOCAB && k + 1 < HID)
                           ? out_W[(size_t)row * HID + k + 1] : 0.f;
            __half2 hh = __floats2half2_rn(v0, v1);
            *(__half2*)(base + ((lanebase + tig) << 4) + ((sub * 2 + hi8) << 2)) = hh;
        }
    }
}

// ---------------------------------------------------------------------------
// Kernel 1: gx via HMMA (3-term split, precision load-bearing). Grid 64.
// ---------------------------------------------------------------------------
#define SMX_BIAS 0
#define SMX_A    1024
#define SMX_B    (SMX_A + 2 * GXM * ROWB)
#define SMX_TOT  (SMX_B + 2 * GXN * ROWB)    // 169984

__global__ __launch_bounds__(256, 1) void gx_mma_kernel(
        const float* __restrict__ b_ih, const float* __restrict__ b_hh) {
    extern __shared__ char sm[];
    const uint32_t sb = smem_u32(sm);
    const int tid = threadIdx.x;
    const int nblk = blockIdx.x & 1, mt = blockIdx.x >> 1;
    const int m0 = mt * GXM, n0 = nblk * GXN;

    for (int c = tid; c < GXN; c += 256) {
        int j = n0 + c;
        ((float*)(sm + SMX_BIAS))[c] = (j < G4) ? b_ih[j] + b_hh[j] : 0.f;
    }
    for (int e = tid; e < 3584; e += 256) {
        int arr = e >= 1792, r = (e - arr * 1792) / 14, c = e % 14;
        const __half* src = (arr ? gE_lo : gE_hi) + (size_t)(m0 + r) * KP + c * 8;
        cp16(sb + SMX_A + arr * 30720 + r * ROWB + c * 16, src);
    }
    for (int e = tid; e < 6272; e += 256) {
        int arr = e >= 3136, r = (e - arr * 3136) / 14, c = e % 14;
        const __half* src = (arr ? gWih_lo : gWih_hi) + (size_t)(n0 + r) * KP + c * 8;
        cp16(sb + SMX_B + arr * 53760 + r * ROWB + c * 16, src);
    }
    asm volatile("cp.async.commit_group;");
    asm volatile("cp.async.wait_group 0;");
    __syncthreads();

    const int wid = tid >> 5, lane = tid & 31;
    const int wm = wid >> 2, wn = wid & 3;
    const int gid = lane >> 2, tig = lane & 3;
    const uint32_t* A32 = (const uint32_t*)(sm + SMX_A);
    const uint32_t* B32 = (const uint32_t*)(sm + SMX_B);

    float acc[4][7][4];
    #pragma unroll
    for (int mb = 0; mb < 4; mb++)
        #pragma unroll
        for (int nb = 0; nb < 7; nb++)
            #pragma unroll
            for (int q = 0; q < 4; q++) acc[mb][nb][q] = 0.f;

    #pragma unroll 1
    for (int ks = 0; ks < 7; ks++) {
        uint32_t ah[4][4], al[4][4];
        #pragma unroll
        for (int mb = 0; mb < 4; mb++) {
            int w = (wm * 64 + mb * 16 + gid) * ROWW + ks * 8 + tig;
            ah[mb][0] = A32[w];            al[mb][0] = A32[w + 7680];
            ah[mb][1] = A32[w + 8 * ROWW]; al[mb][1] = A32[w + 7680 + 8 * ROWW];
            ah[mb][2] = A32[w + 4];        al[mb][2] = A32[w + 7680 + 4];
            ah[mb][3] = A32[w + 8 * ROWW + 4];
            al[mb][3] = A32[w + 7680 + 8 * ROWW + 4];
        }
        #pragma unroll
        for (int nb = 0; nb < 7; nb++) {
            int w = (wn * 56 + nb * 8 + gid) * ROWW + ks * 8 + tig;
            uint32_t bh0 = B32[w], bh1 = B32[w + 4];
            uint32_t bl0 = B32[w + 13440], bl1 = B32[w + 13440 + 4];
            #pragma unroll
            for (int mb = 0; mb < 4; mb++) {
                mma_fp16(acc[mb][nb], ah[mb], bh0, bh1);
                mma_fp16(acc[mb][nb], ah[mb], bl0, bl1);
                mma_fp16(acc[mb][nb], al[mb], bh0, bh1);
            }
        }
    }

    const float* biasS = (const float*)(sm + SMX_BIAS);
    #pragma unroll
    for (int nb = 0; nb < 7; nb++) {
        int jl = wn * 56 + nb * 8 + tig * 2;
        int j  = n0 + jl;
        if (j < G4) {
            float b0 = biasS[jl], b1 = biasS[jl + 1];
            #pragma unroll
            for (int mb = 0; mb < 4; mb++) {
                int row = m0 + wm * 64 + mb * 16 + gid;
                *(float2*)(g_gx + (size_t)row * G4 + j) =
                    make_float2(acc[mb][nb][0] + b0, acc[mb][nb][1] + b1);
                *(float2*)(g_gx + (size_t)(row + 8) * G4 + j) =
                    make_float2(acc[mb][nb][2] + b0, acc[mb][nb][3] + b1);
            }
        }
    }
}

// ---------------------------------------------------------------------------
// Kernel 2 (FUSED): blocks 0..15 = LSTM producer (warp-local gate mapping,
// shfl exchange, double-buffered h, gx prefetched, 4 fma2 chains); publishes
// via red.add.release on ONE flag. blocks 16..147 = persistent fragment-LDG
// GEMM gated by ONE ld.acquire per tile, streaming stores.
// ---------------------------------------------------------------------------
#define FS_BIAS 0                      // 192 floats
#define FS_SEG  1000                   // scratch int (GEMM phase only)
// LSTM smem: h ping@0 (448B), pong@448; h_hist@1024 (3584B); gxbuf@4608
#define LS_HIST 1024
#define LS_GXB  4608
#define LS_GXSZ 25600                  // 16 steps x 400 floats
#define FS_TOT  (LS_GXB + 2 * LS_GXSZ) // 55808

__device__ __forceinline__ void poll_need(int need_steps) {
    // all 16 LSTM CTAs past step s  <=>  g_done >= 2*s  (16 adds per 8 steps)
    if (threadIdx.x == 0) {
        const int need = need_steps * 2;
        while (ld_acq(&g_done) < need) __nanosleep(1024);
    }
    __syncthreads();
}

__global__ __launch_bounds__(416, 1) void fused_kernel(
        const float* __restrict__ W_hh,
        const float* __restrict__ out_b,
        float* __restrict__ out) {
    extern __shared__ char sm[];
    const uint32_t sb = smem_u32(sm);
    const int tid = threadIdx.x;

    if (blockIdx.x < BATCH) {
        // ===================== LSTM producer =====================
        float* h_hist = (float*)(sm + LS_HIST);    // 8 x 112 floats
        const float* gxb = (const float*)(sm + LS_GXB);
        const int b = blockIdx.x;

        const int w_ = tid >> 5, l = tid & 31;
        const int jloc = l & 7, gate = l >> 3;
        const int j = w_ * 8 + jloc;               // hidden unit
        const bool jvalid = (j < HID);
        const int grow = gate * HID + j;           // W_hh row / gx index

        // W row in registers: 100 floats = 25 x ulonglong2 (16B aligned)
        ulonglong2 w4[25];
        if (jvalid) {
            const ulonglong2* wg =
                (const ulonglong2*)(W_hh + (size_t)grow * HID);
            #pragma unroll
            for (int k = 0; k < 25; k++) w4[k] = wg[k];
        }
        if (tid < HID) ((float*)sm)[tid] = 0.f;    // h buf0 = 0
        if (tid < 96) {                            // zero h_hist k-padding
            int s = tid / 12, k = 100 + (tid % 12);
            h_hist[s * KP + k] = 0.f;
        }
        float c = 0.f;

        // prefetch gx chunk 0 (16 steps)
        {
            const uint32_t dst0 = sb + LS_GXB;
            for (int e = tid; e < 1600; e += 416) {
                int row = e / 100, u = e % 100;
                cp16(dst0 + row * 1600 + u * 16,
                     g_gx + ((size_t)row * BATCH + b) * G4 + u * 4);
            }
            asm volatile("cp.async.commit_group;");
            asm volatile("cp.async.wait_group 0;");
        }
        __syncthreads();

        for (int t = 0; t < T_STEPS; t++) {
            if ((t & 15) == 0 && t + 16 < T_STEPS) {
                const int t1 = t + 16;
                const uint32_t dst = sb + LS_GXB + (((t1 >> 4) & 1) ? LS_GXSZ : 0);
                for (int e = tid; e < 1600; e += 416) {
                    int row = e / 100, u = e % 100;
                    cp16(dst + row * 1600 + u * 16,
                         g_gx + ((size_t)(t1 + row) * BATCH + b) * G4 + u * 4);
                }
                asm volatile("cp.async.commit_group;");
            }

            float a = 0.f;
            {
                const ulonglong2* h2 =
                    (const ulonglong2*)(sm + (t & 1) * 448);
                unsigned long long acc0, acc1, acc2, acc3;
                asm("mov.b64 %0, {%1, %1};" : "=l"(acc0) : "r"(0));
                asm("mov.b64 %0, {%1, %1};" : "=l"(acc1) : "r"(0));
                asm("mov.b64 %0, {%1, %1};" : "=l"(acc2) : "r"(0));
                asm("mov.b64 %0, {%1, %1};" : "=l"(acc3) : "r"(0));
                if (jvalid) {
                    #pragma unroll
                    for (int k = 0; k < 25; k++) {
                        ulonglong2 hv = h2[k];
                        if (k & 1) { fma2(acc2, w4[k].x, hv.x);
                                     fma2(acc3, w4[k].y, hv.y); }
                        else       { fma2(acc0, w4[k].x, hv.x);
                                     fma2(acc1, w4[k].y, hv.y); }
                    }
                    float gcur = gxb[((t >> 4) & 1) * 6400 + (t & 15) * 400 + grow];
                    float d = gcur + (unpack_sum(acc0) + unpack_sum(acc1))
                                   + (unpack_sum(acc2) + unpack_sum(acc3));
                    // uniform activation: g-gate tanh(d); others 0.5+0.5*tanh(d/2)
                    float arg = (gate == 2) ? d : 0.5f * d;
                    float th  = tanhf(arg);
                    a = (gate == 2) ? th : (0.5f + 0.5f * th);
                }
            }
            // exchange gates within the warp (all lanes participate)
            float ig = __shfl_sync(0xffffffffu, a, jloc);
            float fg = __shfl_sync(0xffffffffu, a, jloc + 8);
            float gg = __shfl_sync(0xffffffffu, a, jloc + 16);
            float og = __shfl_sync(0xffffffffu, a, jloc + 24);

            if (gate == 0 && jvalid) {
                c = fg * c + ig * gg;
                float hn = og * tanhf(c);
                ((float*)(sm + ((t + 1) & 1) * 448))[j] = hn;
                h_hist[(t & 7) * KP + j] = hn;
            }
            __syncthreads();   // h writes + hist visible; safe to read next step

            if ((t & 7) == 7) {
                // flush 8 steps as fragment-order half2 stores
                if (tid < 224) {
                    const int lane_b = ((b & 7) << 2);
                    const int off_b  = ((b >> 3) << 2);
                    #pragma unroll
                    for (int rep = 0; rep < 2; rep++) {
                        int i  = tid + rep * 224;          // 0..447
                        int s  = i / 56;
                        int kp = i % 56;
                        int ks = kp >> 3, kk = kp & 7;
                        int tg = kk & 3, hi8 = kk >> 2;
                        int kb = ks * 16 + hi8 * 8 + tg * 2;
                        __half2 hh = __floats2half2_rn(
                            h_hist[s * KP + kb], h_hist[s * KP + kb + 1]);
                        char* dst = (char*)gAf +
                            (((size_t)(t - 7 + s) * 7 + ks) << 9) +
                            ((lane_b + tg) << 4) + off_b + (hi8 << 3);
                        *(__half2*)dst = hh;
                    }
                }
                __syncthreads();
                if (tid == 0) red_add_release(&g_done, 1);
            }

            if ((t & 15) == 15 && t + 1 < T_STEPS) {
                asm volatile("cp.async.wait_group 0;");
                __syncthreads();
            }
        }
        __syncthreads();
        // fall through: help the GEMM with remaining segments
    }

    // ===================== GEMM consumer (fragment LDG) =====================
    const int wid = tid >> 5, lane = tid & 31;
    const int wm = (wid < 12) ? (wid / 6) : 0;     // 2(M) x 6(N), warps 0..11
    const int wn = (wid < 12) ? (wid % 6) : 0;
    const int gid = lane >> 2, tig = lane & 3;

    for (;;) {
        if (tid == 0) *(int*)(sm + FS_SEG) = atomicAdd(&g_counter, 1);
        __syncthreads();
        const int seg = *(const int*)(sm + FS_SEG);
        if (seg >= NSEG) break;
        const int mch  = seg / NBLK;          // chunk index (t-ordered)
        const int nblk = seg - mch * NBLK;
        const int n0   = nblk * NT;
        const int mt0  = mch * SEG_M;

        if (tid < NT) {
            int col = n0 + tid;
            ((float*)(sm + FS_BIAS))[tid] = (col < VOCAB) ? out_b[col] : 0.f;
        }

        #pragma unroll 1
        for (int it = 0; it < SEG_M; it++) {
            poll_need((mt0 + it + 1) * 8);   // includes __syncthreads

            if (wid < 12) {
                const int q0  = (mt0 + it) * 8 + wm * 4;   // m16-block base
                const int nb0 = (n0 >> 4) + wn * 2;        // n16-block base

                float acc[4][4][4];
                #pragma unroll
                for (int mb = 0; mb < 4; mb++)
                    #pragma unroll
                    for (int nb = 0; nb < 4; nb++)
                        #pragma unroll
                        for (int q = 0; q < 4; q++) acc[mb][nb][q] = 0.f;

                #pragma unroll
                for (int ks = 0; ks < 7; ks++) {
                    uint4 a[4];
                    #pragma unroll
                    for (int mb = 0; mb < 4; mb++)
                        a[mb] = gAf[((size_t)(q0 + mb) * 7 + ks) * 32 + lane];
                    uint4 B0 = gWf[((size_t)nb0 * 7 + ks) * 32 + lane];
                    uint4 B1 = gWf[((size_t)(nb0 + 1) * 7 + ks) * 32 + lane];

                    #pragma unroll
                    for (int mb = 0; mb < 4; mb++) {
                        const uint32_t* am = (const uint32_t*)&a[mb];
                        mma_fp16(acc[mb][0], am, B0.x, B0.y);
                        mma_fp16(acc[mb][1], am, B0.z, B0.w);
                        mma_fp16(acc[mb][2], am, B1.x, B1.y);
                        mma_fp16(acc[mb][3], am, B1.z, B1.w);
                    }
                }

                const int m0 = (mt0 + it) * MT;
                const float* biasS = (const float*)(sm + FS_BIAS);
                #pragma unroll
                for (int nb = 0; nb < 4; nb++) {
                    int cl  = wn * 32 + nb * 8 + tig * 2;
                    int col = n0 + cl;
                    if (col < VOCAB) {
                        float b0 = biasS[cl], b1 = biasS[cl + 1];
                        #pragma unroll
                        for (int mb = 0; mb < 4; mb++) {
                            int row = m0 + wm * 64 + mb * 16 + gid;
                            stg_cs2(out + (size_t)row * VOCAB + col,
                                    acc[mb][nb][0] + b0, acc[mb][nb][1] + b1);
                            stg_cs2(out + (size_t)(row + 8) * VOCAB + col,
                                    acc[mb][nb][2] + b0, acc[mb][nb][3] + b1);
                        }
                    }
                }
            }
        }
        __syncthreads();   // all reads of bias done before next segment rewrite
    }
}

// ---------------------------------------------------------------------------
// Launch. Inputs: 0 input, 1 emb, 2..5 enc_* (dead), 6 dec_W_ih, 7 dec_W_hh,
// 8 dec_b_ih, 9 dec_b_hh, 10 out_W, 11 out_b.
// ---------------------------------------------------------------------------
extern "C" void kernel_launch(void* const* d_in, const int* in_sizes, int n_in,
                              void* d_out, int out_size) {
    (void)in_sizes; (void)n_in; (void)out_size;
    const int*   input = (const int*)d_in[0];
    const float* emb   = (const float*)d_in[1];
    const float* dWih  = (const float*)d_in[6];
    const float* dWhh  = (const float*)d_in[7];
    const float* dbih  = (const float*)d_in[8];
    const float* dbhh  = (const float*)d_in[9];
    const float* outW  = (const float*)d_in[10];
    const float* outb  = (const float*)d_in[11];
    float* out = (float*)d_out;

    cudaFuncSetAttribute(gx_mma_kernel,
                         cudaFuncAttributeMaxDynamicSharedMemorySize, SMX_TOT);
    cudaFuncSetAttribute(fused_kernel,
                         cudaFuncAttributeMaxDynamicSharedMemorySize, FS_TOT);

    presplit_kernel<<<U_TOT / 256, 256>>>(input, emb, dWih, outW);
    gx_mma_kernel<<<64, 256, SMX_TOT>>>(dbih, dbhh);
    fused_kernel<<<148, 416, FS_TOT>>>(dWhh, outb, out);
}

// round 17
// speedup vs baseline: 1.2236x; 1.0056x over previous
#include <cuda_runtime.h>
#include <cuda_fp16.h>
#include <cstdint>

#define T_STEPS 256
#define BATCH   16
#define HID     100
#define G4      400
#define VOCAB   30522
#define M_ROWS  4096   // T*B
#define KP      112    // K padded to 7 x 16

// Vocab GEMM tiling (fused kernel)
#define MT    128
#define NT    192
#define NBLK  159               // ceil(VOCAB/192)
#define NPAD  (NBLK * NT)       // 30528
#define N16B  (NPAD / 16)       // 1908 n16-blocks
#define SEG_M 4                 // m-tiles per segment -> 512-row chunks
#define NCHK  8
#define NSEG  (NCHK * NBLK)     // 1272
#define ROWB  240               // smem row bytes for gx kernel
#define ROWW  60

// gx GEMM tiling
#define GXM   128
#define GXN   224

// ---------------------------------------------------------------------------
// Device scratch
// ---------------------------------------------------------------------------
__device__ float g_gx[(size_t)M_ROWS * G4];
// A in mma-fragment order: [m16-block q (=t)][ks][lane] -> 16B {a0,a1,a2,a3}
__device__ uint4 gAf[(size_t)T_STEPS * 7 * 32];
// W in mma-fragment order: [n16-block][ks][lane] -> 16B {b0,b1 (n), b0,b1 (n+8)}
__device__ uint4 gWf[(size_t)N16B * 7 * 32];
__device__ __align__(16) __half gE_hi[(size_t)M_ROWS * KP];
__device__ __align__(16) __half gE_lo[(size_t)M_ROWS * KP];
__device__ __align__(16) __half gWih_hi[(size_t)448 * KP];
__device__ __align__(16) __half gWih_lo[(size_t)448 * KP];
__device__ int g_counter;
__device__ int g_done;           // SINGLE progress flag: +1 per LSTM CTA per 8 steps

// ---------------------------------------------------------------------------
// helpers
// ---------------------------------------------------------------------------
__device__ __forceinline__ uint32_t smem_u32(const void* p) {
    uint32_t a;
    asm("{ .reg .u64 t; cvta.to.shared.u64 t, %1; cvt.u32.u64 %0, t; }"
        : "=r"(a) : "l"(p));
    return a;
}
__device__ __forceinline__ void cp16(uint32_t dst, const void* src) {
    asm volatile("cp.async.ca.shared.global [%0], [%1], 16;" :: "r"(dst), "l"(src));
}
__device__ __forceinline__ void mma_fp16(float* c, const uint32_t* a,
                                         uint32_t b0, uint32_t b1) {
    asm volatile(
        "mma.sync.aligned.m16n8k16.row.col.f32.f16.f16.f32 "
        "{%0,%1,%2,%3},{%4,%5,%6,%7},{%8,%9},{%0,%1,%2,%3};\n"
        : "+f"(c[0]), "+f"(c[1]), "+f"(c[2]), "+f"(c[3])
        : "r"(a[0]), "r"(a[1]), "r"(a[2]), "r"(a[3]), "r"(b0), "r"(b1));
}
#define LDS128V(r, a) \
    asm volatile("ld.shared.v4.b32 {%0,%1,%2,%3}, [%4];" \
        : "=r"((r)[0]), "=r"((r)[1]), "=r"((r)[2]), "=r"((r)[3]) : "r"(a))
__device__ __forceinline__ void stg_cs2(float* p, float x, float y) {
    asm volatile("st.global.cs.v2.f32 [%0], {%1, %2};"
                 :: "l"(p), "f"(x), "f"(y) : "memory");
}
__device__ __forceinline__ void fma2(unsigned long long& acc,
                                     unsigned long long a,
                                     unsigned long long b) {
    asm("fma.rn.f32x2 %0, %1, %2, %0;" : "+l"(acc) : "l"(a), "l"(b));
}
__device__ __forceinline__ float unpack_sum(unsigned long long a) {
    float lo, hi;
    asm("mov.b64 {%0, %1}, %2;" : "=f"(lo), "=f"(hi) : "l"(a));
    return lo + hi;
}

__device__ __forceinline__ void split8(const float* v, uint32_t* ph, uint32_t* pl) {
    #pragma unroll
    for (int j = 0; j < 4; j++) {
        __half h0 = __float2half_rn(v[2*j]);
        __half h1 = __float2half_rn(v[2*j+1]);
        __half l0 = __float2half_rn(v[2*j]   - __half2float(h0));
        __half l1 = __float2half_rn(v[2*j+1] - __half2float(h1));
        ph[j] = (uint32_t)__half_as_ushort(h0) | ((uint32_t)__half_as_ushort(h1) << 16);
        pl[j] = (uint32_t)__half_as_ushort(l0) | ((uint32_t)__half_as_ushort(l1) << 16);
    }
}
__device__ __forceinline__ int ld_acq(const int* p) {
    int v;
    asm volatile("ld.acquire.gpu.global.b32 %0, [%1];" : "=r"(v) : "l"(p) : "memory");
    return v;
}
__device__ __forceinline__ void red_add_release(int* p, int v) {
    asm volatile("red.add.release.gpu.global.s32 [%0], %1;"
                 :: "l"(p), "r"(v) : "memory");
}

// ---------------------------------------------------------------------------
// Kernel 0: presplit. emb gather -> gE hi/lo; W_ih -> gWih hi/lo;
// out_W -> gWf (fragment order, fp16 hi). + reset counter/progress.
// ---------------------------------------------------------------------------
#define U_E    (M_ROWS * 14)
#define U_WIH  (448 * 14)
#define U_W    (NPAD * 14)
#define U_TOT  (U_E + U_WIH + U_W)           // 491008 = 1918*256

__global__ __launch_bounds__(256) void presplit_kernel(
        const int* __restrict__ input, const float* __restrict__ emb,
        const float* __restrict__ dec_W_ih, const float* __restrict__ out_W) {
    if (blockIdx.x == 0) {
        if (threadIdx.x == 0) g_done = 0;
        if (threadIdx.x == 1) g_counter = 0;
    }
    const int u = blockIdx.x * 256 + threadIdx.x;
    float v[8];
    uint32_t ph[4], pl[4];

    if (u < U_E) {
        int row = u / 14, k0 = (u % 14) * 8;
        const float* src = emb + (size_t)input[row] * HID;
        #pragma unroll
        for (int i = 0; i < 8; i++) {
            int k = k0 + i;
            v[i] = (k < HID) ? src[k] : 0.f;
        }
        split8(v, ph, pl);
        size_t d = (size_t)row * KP + k0;
        *(uint4*)(gE_hi + d) = make_uint4(ph[0], ph[1], ph[2], ph[3]);
        *(uint4*)(gE_lo + d) = make_uint4(pl[0], pl[1], pl[2], pl[3]);
    } else if (u < U_E + U_WIH) {
        int w = u - U_E;
        int row = w / 14, k0 = (w % 14) * 8;
        #pragma unroll
        for (int i = 0; i < 8; i++) {
            int k = k0 + i;
            v[i] = (row < G4 && k < HID) ? dec_W_ih[(size_t)row * HID + k] : 0.f;
        }
        split8(v, ph, pl);
        size_t d = (size_t)row * KP + k0;
        *(uint4*)(gWih_hi + d) = make_uint4(ph[0], ph[1], ph[2], ph[3]);
        *(uint4*)(gWih_lo + d) = make_uint4(pl[0], pl[1], pl[2], pl[3]);
    } else {
        // out_W row 'row', k-unit of 8 -> fragment-order half2 stores
        int w = u - U_E - U_WIH;
        int row = w / 14, k0 = (w % 14) * 8;
        int ks = k0 >> 4, hi8 = (k0 >> 3) & 1;
        int nb16 = row >> 4, sub = (row >> 3) & 1;
        int lanebase = (row & 7) << 2;
        char* base = (char*)gWf + ((((size_t)nb16 * 7 + ks) << 9));
        #pragma unroll
        for (int tig = 0; tig < 4; tig++) {
            int k = k0 + tig * 2;
            float v0 = (row < VOCAB && k < HID)
                           ? out_W[(size_t)row * HID + k] : 0.f;
            float v1 = (row < VOCAB && k + 1 < HID)
                           ? out_W[(size_t)row * HID + k + 1] : 0.f;
            __half2 hh = __floats2half2_rn(v0, v1);
            *(__half2*)(base + ((lanebase + tig) << 4) + ((sub * 2 + hi8) << 2)) = hh;
        }
    }
}

// ---------------------------------------------------------------------------
// Kernel 1: gx via HMMA (3-term split, precision load-bearing). Grid 64.
// ---------------------------------------------------------------------------
#define SMX_BIAS 0
#define SMX_A    1024
#define SMX_B    (SMX_A + 2 * GXM * ROWB)
#define SMX_TOT  (SMX_B + 2 * GXN * ROWB)    // 169984

__global__ __launch_bounds__(256, 1) void gx_mma_kernel(
        const float* __restrict__ b_ih, const float* __restrict__ b_hh) {
    extern __shared__ char sm[];
    const uint32_t sb = smem_u32(sm);
    const int tid = threadIdx.x;
    const int nblk = blockIdx.x & 1, mt = blockIdx.x >> 1;
    const int m0 = mt * GXM, n0 = nblk * GXN;

    for (int c = tid; c < GXN; c += 256) {
        int j = n0 + c;
        ((float*)(sm + SMX_BIAS))[c] = (j < G4) ? b_ih[j] + b_hh[j] : 0.f;
    }
    for (int e = tid; e < 3584; e += 256) {
        int arr = e >= 1792, r = (e - arr * 1792) / 14, c = e % 14;
        const __half* src = (arr ? gE_lo : gE_hi) + (size_t)(m0 + r) * KP + c * 8;
        cp16(sb + SMX_A + arr * 30720 + r * ROWB + c * 16, src);
    }
    for (int e = tid; e < 6272; e += 256) {
        int arr = e >= 3136, r = (e - arr * 3136) / 14, c = e % 14;
        const __half* src = (arr ? gWih_lo : gWih_hi) + (size_t)(n0 + r) * KP + c * 8;
        cp16(sb + SMX_B + arr * 53760 + r * ROWB + c * 16, src);
    }
    asm volatile("cp.async.commit_group;");
    asm volatile("cp.async.wait_group 0;");
    __syncthreads();

    const int wid = tid >> 5, lane = tid & 31;
    const int wm = wid >> 2, wn = wid & 3;
    const int gid = lane >> 2, tig = lane & 3;
    const uint32_t* A32 = (const uint32_t*)(sm + SMX_A);
    const uint32_t* B32 = (const uint32_t*)(sm + SMX_B);

    float acc[4][7][4];
    #pragma unroll
    for (int mb = 0; mb < 4; mb++)
        #pragma unroll
        for (int nb = 0; nb < 7; nb++)
            #pragma unroll
            for (int q = 0; q < 4; q++) acc[mb][nb][q] = 0.f;

    #pragma unroll 1
    for (int ks = 0; ks < 7; ks++) {
        uint32_t ah[4][4], al[4][4];
        #pragma unroll
        for (int mb = 0; mb < 4; mb++) {
            int w = (wm * 64 + mb * 16 + gid) * ROWW + ks * 8 + tig;
            ah[mb][0] = A32[w];            al[mb][0] = A32[w + 7680];
            ah[mb][1] = A32[w + 8 * ROWW]; al[mb][1] = A32[w + 7680 + 8 * ROWW];
            ah[mb][2] = A32[w + 4];        al[mb][2] = A32[w + 7680 + 4];
            ah[mb][3] = A32[w + 8 * ROWW + 4];
            al[mb][3] = A32[w + 7680 + 8 * ROWW + 4];
        }
        #pragma unroll
        for (int nb = 0; nb < 7; nb++) {
            int w = (wn * 56 + nb * 8 + gid) * ROWW + ks * 8 + tig;
            uint32_t bh0 = B32[w], bh1 = B32[w + 4];
            uint32_t bl0 = B32[w + 13440], bl1 = B32[w + 13440 + 4];
            #pragma unroll
            for (int mb = 0; mb < 4; mb++) {
                mma_fp16(acc[mb][nb], ah[mb], bh0, bh1);
                mma_fp16(acc[mb][nb], ah[mb], bl0, bl1);
                mma_fp16(acc[mb][nb], al[mb], bh0, bh1);
            }
        }
    }

    const float* biasS = (const float*)(sm + SMX_BIAS);
    #pragma unroll
    for (int nb = 0; nb < 7; nb++) {
        int jl = wn * 56 + nb * 8 + tig * 2;
        int j  = n0 + jl;
        if (j < G4) {
            float b0 = biasS[jl], b1 = biasS[jl + 1];
            #pragma unroll
            for (int mb = 0; mb < 4; mb++) {
                int row = m0 + wm * 64 + mb * 16 + gid;
                *(float2*)(g_gx + (size_t)row * G4 + j) =
                    make_float2(acc[mb][nb][0] + b0, acc[mb][nb][1] + b1);
                *(float2*)(g_gx + (size_t)(row + 8) * G4 + j) =
                    make_float2(acc[mb][nb][2] + b0, acc[mb][nb][3] + b1);
            }
        }
    }
}

// ---------------------------------------------------------------------------
// Kernel 2 (FUSED): blocks 0..15 = LSTM producer (unchanged R16); blocks
// 16..147 = persistent GEMM, now with smem-staged fragments: B once per
// segment (43KB), A once per tile (28.7KB, double-buffered) via cp.async.
// Compute reads fragments via conflict-free lds.128. Streaming stores.
// ---------------------------------------------------------------------------
#define FS_BIAS 0                      // 192 floats
#define FS_SEG  1000                   // scratch int (GEMM phase only)
#define FS_A    2048                   // 2 x 28672 A-fragment buffers
#define FS_ABUF 28672
#define FS_B    (FS_A + 2 * FS_ABUF)   // 59392; B fragments 43008
#define FS_TOT  (FS_B + 43008)         // 102400
// LSTM smem (disjoint phase): h ping@0/pong@448; h_hist@1024; gxbuf@4608
#define LS_HIST 1024
#define LS_GXB  4608
#define LS_GXSZ 25600                  // 16 steps x 400 floats

__device__ __forceinline__ void poll_need(int need_steps) {
    // all 16 LSTM CTAs past step s  <=>  g_done >= 2*s  (16 adds per 8 steps)
    if (threadIdx.x == 0) {
        const int need = need_steps * 2;
        while (ld_acq(&g_done) < need) __nanosleep(1024);
    }
    __syncthreads();
}

__global__ __launch_bounds__(416, 1) void fused_kernel(
        const float* __restrict__ W_hh,
        const float* __restrict__ out_b,
        float* __restrict__ out) {
    extern __shared__ char sm[];
    const uint32_t sb = smem_u32(sm);
    const int tid = threadIdx.x;

    if (blockIdx.x < BATCH) {
        // ===================== LSTM producer (R16, frozen) =====================
        float* h_hist = (float*)(sm + LS_HIST);    // 8 x 112 floats
        const float* gxb = (const float*)(sm + LS_GXB);
        const int b = blockIdx.x;

        const int w_ = tid >> 5, l = tid & 31;
        const int jloc = l & 7, gate = l >> 3;
        const int j = w_ * 8 + jloc;               // hidden unit
        const bool jvalid = (j < HID);
        const int grow = gate * HID + j;           // W_hh row / gx index

        ulonglong2 w4[25];
        if (jvalid) {
            const ulonglong2* wg =
                (const ulonglong2*)(W_hh + (size_t)grow * HID);
            #pragma unroll
            for (int k = 0; k < 25; k++) w4[k] = wg[k];
        }
        if (tid < HID) ((float*)sm)[tid] = 0.f;    // h buf0 = 0
        if (tid < 96) {                            // zero h_hist k-padding
            int s = tid / 12, k = 100 + (tid % 12);
            h_hist[s * KP + k] = 0.f;
        }
        float c = 0.f;

        {
            const uint32_t dst0 = sb + LS_GXB;
            for (int e = tid; e < 1600; e += 416) {
                int row = e / 100, u = e % 100;
                cp16(dst0 + row * 1600 + u * 16,
                     g_gx + ((size_t)row * BATCH + b) * G4 + u * 4);
            }
            asm volatile("cp.async.commit_group;");
            asm volatile("cp.async.wait_group 0;");
        }
        __syncthreads();

        for (int t = 0; t < T_STEPS; t++) {
            if ((t & 15) == 0 && t + 16 < T_STEPS) {
                const int t1 = t + 16;
                const uint32_t dst = sb + LS_GXB + (((t1 >> 4) & 1) ? LS_GXSZ : 0);
                for (int e = tid; e < 1600; e += 416) {
                    int row = e / 100, u = e % 100;
                    cp16(dst + row * 1600 + u * 16,
                         g_gx + ((size_t)(t1 + row) * BATCH + b) * G4 + u * 4);
                }
                asm volatile("cp.async.commit_group;");
            }

            float a = 0.f;
            {
                const ulonglong2* h2 =
                    (const ulonglong2*)(sm + (t & 1) * 448);
                unsigned long long acc0, acc1, acc2, acc3;
                asm("mov.b64 %0, {%1, %1};" : "=l"(acc0) : "r"(0));
                asm("mov.b64 %0, {%1, %1};" : "=l"(acc1) : "r"(0));
                asm("mov.b64 %0, {%1, %1};" : "=l"(acc2) : "r"(0));
                asm("mov.b64 %0, {%1, %1};" : "=l"(acc3) : "r"(0));
                if (jvalid) {
                    #pragma unroll
                    for (int k = 0; k < 25; k++) {
                        ulonglong2 hv = h2[k];
                        if (k & 1) { fma2(acc2, w4[k].x, hv.x);
                                     fma2(acc3, w4[k].y, hv.y); }
                        else       { fma2(acc0, w4[k].x, hv.x);
                                     fma2(acc1, w4[k].y, hv.y); }
                    }
                    float gcur = gxb[((t >> 4) & 1) * 6400 + (t & 15) * 400 + grow];
                    float d = gcur + (unpack_sum(acc0) + unpack_sum(acc1))
                                   + (unpack_sum(acc2) + unpack_sum(acc3));
                    float arg = (gate == 2) ? d : 0.5f * d;
                    float th  = tanhf(arg);
                    a = (gate == 2) ? th : (0.5f + 0.5f * th);
                }
            }
            float ig = __shfl_sync(0xffffffffu, a, jloc);
            float fg = __shfl_sync(0xffffffffu, a, jloc + 8);
            float gg = __shfl_sync(0xffffffffu, a, jloc + 16);
            float og = __shfl_sync(0xffffffffu, a, jloc + 24);

            if (gate == 0 && jvalid) {
                c = fg * c + ig * gg;
                float hn = og * tanhf(c);
                ((float*)(sm + ((t + 1) & 1) * 448))[j] = hn;
                h_hist[(t & 7) * KP + j] = hn;
            }
            __syncthreads();

            if ((t & 7) == 7) {
                if (tid < 224) {
                    const int lane_b = ((b & 7) << 2);
                    const int off_b  = ((b >> 3) << 2);
                    #pragma unroll
                    for (int rep = 0; rep < 2; rep++) {
                        int i  = tid + rep * 224;          // 0..447
                        int s  = i / 56;
                        int kp = i % 56;
                        int ks = kp >> 3, kk = kp & 7;
                        int tg = kk & 3, hi8 = kk >> 2;
                        int kb = ks * 16 + hi8 * 8 + tg * 2;
                        __half2 hh = __floats2half2_rn(
                            h_hist[s * KP + kb], h_hist[s * KP + kb + 1]);
                        char* dst = (char*)gAf +
                            (((size_t)(t - 7 + s) * 7 + ks) << 9) +
                            ((lane_b + tg) << 4) + off_b + (hi8 << 3);
                        *(__half2*)dst = hh;
                    }
                }
                __syncthreads();
                if (tid == 0) red_add_release(&g_done, 1);
            }

            if ((t & 15) == 15 && t + 1 < T_STEPS) {
                asm volatile("cp.async.wait_group 0;");
                __syncthreads();
            }
        }
        __syncthreads();
        // fall through: help the GEMM with remaining segments
    }

    // ===================== GEMM consumer (smem-staged fragments) ============
    const int wid = tid >> 5, lane = tid & 31;
    const int wm = (wid < 12) ? (wid / 6) : 0;     // 2(M) x 6(N), warps 0..11
    const int wn = (wid < 12) ? (wid % 6) : 0;
    const int gid = lane >> 2, tig = lane & 3;
    const uint32_t lane16 = (uint32_t)lane * 16;

    for (;;) {
        if (tid == 0) *(int*)(sm + FS_SEG) = atomicAdd(&g_counter, 1);
        __syncthreads();
        const int seg = *(const int*)(sm + FS_SEG);
        if (seg >= NSEG) break;
        const int mch  = seg / NBLK;          // chunk index (t-ordered)
        const int nblk = seg - mch * NBLK;
        const int n0   = nblk * NT;
        const int mt0  = mch * SEG_M;

        if (tid < NT) {
            int col = n0 + tid;
            ((float*)(sm + FS_BIAS))[tid] = (col < VOCAB) ? out_b[col] : 0.f;
        }
        // stage B fragments for the whole segment (contiguous 2688 x 16B)
        {
            const char* bsrc = (const char*)(gWf + (size_t)(n0 >> 4) * 7 * 32);
            for (int e = tid; e < 2688; e += 416)
                cp16(sb + FS_B + e * 16, bsrc + (size_t)e * 16);
            asm volatile("cp.async.commit_group;");
        }
        // gate tile 0, stage A0 (contiguous 1792 x 16B)
        poll_need((mt0 + 1) * 8);
        {
            const char* asrc = (const char*)(gAf + (size_t)(mt0 * 8) * 7 * 32);
            for (int e = tid; e < 1792; e += 416)
                cp16(sb + FS_A + e * 16, asrc + (size_t)e * 16);
            asm volatile("cp.async.commit_group;");
            asm volatile("cp.async.wait_group 0;");
        }
        __syncthreads();

        #pragma unroll 1
        for (int it = 0; it < SEG_M; it++) {
            if (it < SEG_M - 1) {   // gate + prefetch A(it+1) into other buffer
                poll_need((mt0 + it + 2) * 8);
                const char* asrc =
                    (const char*)(gAf + (size_t)((mt0 + it + 1) * 8) * 7 * 32);
                const uint32_t abase = sb + FS_A + ((it + 1) & 1) * FS_ABUF;
                for (int e = tid; e < 1792; e += 416)
                    cp16(abase + e * 16, asrc + (size_t)e * 16);
                asm volatile("cp.async.commit_group;");
            }

            if (wid < 12) {
                const uint32_t aBase = sb + FS_A + (it & 1) * FS_ABUF +
                                       (uint32_t)(wm * 4) * 7 * 512 + lane16;
                const uint32_t b0Base = sb + FS_B +
                                        (uint32_t)(wn * 2) * 7 * 512 + lane16;

                float acc[4][4][4];
                #pragma unroll
                for (int mb = 0; mb < 4; mb++)
                    #pragma unroll
                    for (int nb = 0; nb < 4; nb++)
                        #pragma unroll
                        for (int q = 0; q < 4; q++) acc[mb][nb][q] = 0.f;

                #pragma unroll
                for (int ks = 0; ks < 7; ks++) {
                    uint32_t a[4][4], B0[4], B1[4];
                    #pragma unroll
                    for (int mb = 0; mb < 4; mb++)
                        LDS128V(a[mb], aBase + (mb * 7 + ks) * 512);
                    LDS128V(B0, b0Base + ks * 512);
                    LDS128V(B1, b0Base + (7 + ks) * 512);

                    #pragma unroll
                    for (int mb = 0; mb < 4; mb++) {
                        mma_fp16(acc[mb][0], a[mb], B0[0], B0[1]);
                        mma_fp16(acc[mb][1], a[mb], B0[2], B0[3]);
                        mma_fp16(acc[mb][2], a[mb], B1[0], B1[1]);
                        mma_fp16(acc[mb][3], a[mb], B1[2], B1[3]);
                    }
                }

                const int m0 = (mt0 + it) * MT;
                const float* biasS = (const float*)(sm + FS_BIAS);
                #pragma unroll
                for (int nb = 0; nb < 4; nb++) {
                    int cl  = wn * 32 + nb * 8 + tig * 2;
                    int col = n0 + cl;
                    if (col < VOCAB) {
                        float b0 = biasS[cl], b1 = biasS[cl + 1];
                        #pragma unroll
                        for (int mb = 0; mb < 4; mb++) {
                            int row = m0 + wm * 64 + mb * 16 + gid;
                            stg_cs2(out + (size_t)row * VOCAB + col,
                                    acc[mb][nb][0] + b0, acc[mb][nb][1] + b1);
                            stg_cs2(out + (size_t)(row + 8) * VOCAB + col,
                                    acc[mb][nb][2] + b0, acc[mb][nb][3] + b1);
                        }
                    }
                }
            }

            if (it < SEG_M - 1) asm volatile("cp.async.wait_group 0;");
            __syncthreads();
        }
    }
}

// ---------------------------------------------------------------------------
// Launch. Inputs: 0 input, 1 emb, 2..5 enc_* (dead), 6 dec_W_ih, 7 dec_W_hh,
// 8 dec_b_ih, 9 dec_b_hh, 10 out_W, 11 out_b.
// ---------------------------------------------------------------------------
extern "C" void kernel_launch(void* const* d_in, const int* in_sizes, int n_in,
                              void* d_out, int out_size) {
    (void)in_sizes; (void)n_in; (void)out_size;
    const int*   input = (const int*)d_in[0];
    const float* emb   = (const float*)d_in[1];
    const float* dWih  = (const float*)d_in[6];
    const float* dWhh  = (const float*)d_in[7];
    const float* dbih  = (const float*)d_in[8];
    const float* dbhh  = (const float*)d_in[9];
    const float* outW  = (const float*)d_in[10];
    const float* outb  = (const float*)d_in[11];
    float* out = (float*)d_out;

    cudaFuncSetAttribute(gx_mma_kernel,
                         cudaFuncAttributeMaxDynamicSharedMemorySize, SMX_TOT);
    cudaFuncSetAttribute(fused_kernel,
                         cudaFuncAttributeMaxDynamicSharedMemorySize, FS_TOT);

    presplit_kernel<<<U_TOT / 256, 256>>>(input, emb, dWih, outW);
    gx_mma_kernel<<<64, 256, SMX_TOT>>>(dbih, dbhh);
    fused_kernel<<<148, 416, FS_TOT>>>(dWhh, outb, out);
}